// round 16
// baseline (speedup 1.0000x reference)
#include <cuda_runtime.h>
#include <cstdint>

#define TPB   128
#define TOKT  16                 // tokens per tile
#define NTILE 1024
#define EXPN  64
#define CDIM  2048
#define BT    16384
#define TOPK  6
#define LSTRE 65

#define WBUF  (64 * 132)         // 8448 floats per W buffer
#define XBUF  (TOKT * 132)       // 2112 floats per x buffer
#define SMEM_FLOATS (2 * WBUF + 2 * XBUF)
#define SMEM_BYTES  (SMEM_FLOATS * 4)   // 84480

__device__ float g_part[NTILE * EXPN];   // per-tile expert prob sums
__device__ float g_pcnt[NTILE * EXPN];   // per-tile expert top-k counts

static __device__ __forceinline__ void cp16(void* smem_ptr, const void* gptr) {
    unsigned saddr = (unsigned)__cvta_generic_to_shared(smem_ptr);
    asm volatile("cp.async.cg.shared.global [%0], [%1], 16;\n" :: "r"(saddr), "l"(gptr));
}
#define CP_COMMIT() asm volatile("cp.async.commit_group;\n" ::: "memory")

static __device__ __forceinline__ void ffma2(unsigned long long& d,
                                             unsigned long long a, unsigned long long b) {
    asm("fma.rn.f32x2 %0, %1, %2, %0;" : "+l"(d) : "l"(a), "l"(b));
}
static __device__ __forceinline__ void unpk(unsigned long long v, float& lo, float& hi) {
    asm("mov.b64 {%0, %1}, %2;" : "=f"(lo), "=f"(hi) : "l"(v));
}

// ---------------- main: exact fp32 logits (R1 realization) + fused epilogue ----------------
__global__ void __launch_bounds__(TPB, 2)
gate_kernel(const float* __restrict__ x, const float* __restrict__ w,
            float* __restrict__ out) {
    extern __shared__ float sm[];
    float* ws = sm;                     // 2 x (64 x 132)
    float* xs = sm + 2 * WBUF;          // 2 x (16 x 132)
    float* lsm = sm;                    // aliases W buffer 0 after mainloop

    __shared__ float s_sums[EXPN];
    __shared__ float s_cnt[EXPN];

    const int tid  = threadIdx.x;
    const int wid  = tid >> 5;
    const int lane = tid & 31;
    const int tile = blockIdx.x;
    const int tok0 = tile * TOKT;

    if (tid < EXPN) { s_sums[tid] = 0.f; s_cnt[tid] = 0.f; }

    const int tok_l = wid * 4 + (lane >> 3);   // 0..15 local token
    const int eg    = lane & 7;                // expert group

    unsigned long long acc[8];
#pragma unroll
    for (int q = 0; q < 8; q++) acc[q] = 0ULL;

    auto load_chunk = [&](int c) {
        const int par = c & 1;
        float* wd = ws + par * WBUF;
        float* xd = xs + par * XBUF;
#pragma unroll
        for (int j = 0; j < 16; j++) {       // 2048 float4 of W
            int idx = tid + j * TPB;
            int e = idx >> 5, q = idx & 31;
            cp16(wd + e * 132 + q * 4, w + (size_t)e * CDIM + c * 128 + q * 4);
        }
#pragma unroll
        for (int j = 0; j < 4; j++) {        // 512 float4 of x
            int idx = tid + j * TPB;
            int t = idx >> 5, q = idx & 31;
            cp16(xd + t * 132 + q * 4, x + (size_t)(tok0 + t) * CDIM + c * 128 + q * 4);
        }
        CP_COMMIT();
    };

    load_chunk(0);
    load_chunk(1);

    for (int c = 0; c < 16; c++) {
        if (c + 1 < 16) asm volatile("cp.async.wait_group 1;\n" ::: "memory");
        else            asm volatile("cp.async.wait_group 0;\n" ::: "memory");
        __syncthreads();

        const int par = c & 1;
        const float* xrow = xs + par * XBUF + tok_l * 132;
        const float* wb   = ws + par * WBUF + eg * 132;

#pragma unroll 8
        for (int kq = 0; kq < 32; kq++) {
            ulonglong2 xv = *(const ulonglong2*)(xrow + kq * 4);
            ulonglong2 wv[8];
#pragma unroll
            for (int q = 0; q < 8; q++)
                wv[q] = *(const ulonglong2*)(wb + q * (8 * 132) + kq * 4);
#pragma unroll
            for (int q = 0; q < 8; q++) ffma2(acc[q], xv.x, wv[q].x);
#pragma unroll
            for (int q = 0; q < 8; q++) ffma2(acc[q], xv.y, wv[q].y);
        }
        __syncthreads();
        if (c + 2 < 16) load_chunk(c + 2);
    }

    // logits -> smem (lo+hi = R1's even-chain + odd-chain sum)
#pragma unroll
    for (int q = 0; q < 8; q++) {
        float lo, hi;
        unpk(acc[q], lo, hi);
        lsm[tok_l * LSTRE + eg + 8 * q] = lo + hi;
    }
    __syncthreads();

    // ---- per-token epilogue: R1-verbatim top-6 + softmax + outputs + aux partials ----
    if (tid < TOKT) {
        float* row = lsm + tid * LSTRE;

        float v0 = -1e38f, v1 = -1e38f, v2 = -1e38f, v3 = -1e38f, v4 = -1e38f, v5 = -1e38f;
        int   i0 = 0, i1 = 0, i2 = 0, i3 = 0, i4 = 0, i5 = 0;
        for (int e = 0; e < EXPN; e++) {
            float l = row[e];
            if (l > v5) {
                v5 = l; i5 = e;
                if (v5 > v4) { float t = v4; v4 = v5; v5 = t; int u = i4; i4 = i5; i5 = u; }
                if (v4 > v3) { float t = v3; v3 = v4; v4 = t; int u = i3; i3 = i4; i4 = u; }
                if (v3 > v2) { float t = v2; v2 = v3; v3 = t; int u = i2; i2 = i3; i3 = u; }
                if (v2 > v1) { float t = v1; v1 = v2; v2 = t; int u = i1; i1 = i2; i2 = u; }
                if (v1 > v0) { float t = v0; v0 = v1; v1 = t; int u = i0; i0 = i1; i1 = u; }
            }
        }

        float m = v0;
        float ssum = 0.f;
        for (int e = 0; e < EXPN; e++) {
            float p = expf(row[e] - m);
            ssum += p;
            row[e] = p;
        }
        float inv = 1.0f / ssum;

        const size_t g = (size_t)(tok0 + tid);
        float* out_idx = out;
        float* out_wgt = out + (size_t)BT * TOPK;

        out_idx[g * TOPK + 0] = (float)i0;
        out_idx[g * TOPK + 1] = (float)i1;
        out_idx[g * TOPK + 2] = (float)i2;
        out_idx[g * TOPK + 3] = (float)i3;
        out_idx[g * TOPK + 4] = (float)i4;
        out_idx[g * TOPK + 5] = (float)i5;

        out_wgt[g * TOPK + 0] = row[i0] * inv;
        out_wgt[g * TOPK + 1] = row[i1] * inv;
        out_wgt[g * TOPK + 2] = row[i2] * inv;
        out_wgt[g * TOPK + 3] = row[i3] * inv;
        out_wgt[g * TOPK + 4] = row[i4] * inv;
        out_wgt[g * TOPK + 5] = row[i5] * inv;

        for (int jj = 0; jj < EXPN; jj++) {
            int e = (tid + jj) & (EXPN - 1);
            atomicAdd(&s_sums[e], row[e] * inv);
        }
        atomicAdd(&s_cnt[i0], 1.0f);
        atomicAdd(&s_cnt[i1], 1.0f);
        atomicAdd(&s_cnt[i2], 1.0f);
        atomicAdd(&s_cnt[i3], 1.0f);
        atomicAdd(&s_cnt[i4], 1.0f);
        atomicAdd(&s_cnt[i5], 1.0f);
    }
    __syncthreads();

    // per-tile partials (overwrite — no zeroing kernel needed)
    if (tid < EXPN) {
        g_part[tile * EXPN + tid] = s_sums[tid];
        g_pcnt[tile * EXPN + tid] = s_cnt[tid];
    }
}

// ---------------- aux: reduce per-tile partials ----------------
__global__ void aux_kernel(float* __restrict__ out) {
    __shared__ float red[256];
    const int tid = threadIdx.x;
    const int b = tid >> 6;     // batch element (tiles b*256 .. b*256+255)
    const int e = tid & 63;

    float ssum = 0.f, csum = 0.f;
    for (int t = 0; t < 256; t++) {
        int idx = (b * 256 + t) * EXPN + e;
        ssum += g_part[idx];
        csum += g_pcnt[idx];
    }
    red[tid] = ssum * csum;
    __syncthreads();
#pragma unroll
    for (int s = 128; s > 0; s >>= 1) {
        if (tid < s) red[tid] += red[tid + s];
        __syncthreads();
    }
    if (tid == 0) {
        const float scale = (float)(0.001 * 64.0 / ((double)4 * 4096.0 * 6.0 * 4096.0));
        out[(size_t)BT * 12] = red[0] * scale;
    }
}

extern "C" void kernel_launch(void* const* d_in, const int* in_sizes, int n_in,
                              void* d_out, int out_size) {
    const float* x = (const float*)d_in[0];
    const float* w = (const float*)d_in[1];
    float* out = (float*)d_out;

    cudaFuncSetAttribute(gate_kernel, cudaFuncAttributeMaxDynamicSharedMemorySize, SMEM_BYTES);

    gate_kernel<<<NTILE, TPB, SMEM_BYTES>>>(x, w, out);
    aux_kernel<<<1, 256>>>(out);
}

// round 17
// speedup vs baseline: 2.0783x; 2.0783x over previous
#include <cuda_runtime.h>
#include <cstdint>

#define TPB   32
#define TOKT  16
#define NTILE 1024
#define EXPN  64
#define CDIM  2048
#define BT    16384
#define TOPK  6
#define KC    32                  // k per chunk
#define NCHK  64
#define WROW  36                  // padded row stride (floats)
#define WBUF  (64 * WROW)         // 2304 floats
#define XBUF  (TOKT * WROW)       // 576 floats
#define SMEM_BYTES ((2 * WBUF + 2 * XBUF) * 4)   // 23040
#define LSTRE 65

__device__ float g_part[NTILE * EXPN];
__device__ float g_pcnt[NTILE * EXPN];

static __device__ __forceinline__ void cp16(void* smem_ptr, const void* gptr) {
    unsigned saddr = (unsigned)__cvta_generic_to_shared(smem_ptr);
    asm volatile("cp.async.cg.shared.global [%0], [%1], 16;\n" :: "r"(saddr), "l"(gptr));
}
#define CP_COMMIT() asm volatile("cp.async.commit_group;\n" ::: "memory")

static __device__ __forceinline__ void ffma2(unsigned long long& d,
                                             unsigned long long a, unsigned long long b) {
    asm("fma.rn.f32x2 %0, %1, %2, %0;" : "+l"(d) : "l"(a), "l"(b));
}
static __device__ __forceinline__ void unpk(unsigned long long v, float& lo, float& hi) {
    asm("mov.b64 {%0, %1}, %2;" : "=f"(lo), "=f"(hi) : "l"(v));
}

// ---------------- gate: exact fp32 logits (R1-bit-identical) + fused epilogue ----------------
__global__ void __launch_bounds__(TPB)
gate_kernel(const float* __restrict__ x, const float* __restrict__ w,
            float* __restrict__ out) {
    extern __shared__ float sm[];
    float* ws = sm;                 // 2 x (64 x 36)
    float* xs = sm + 2 * WBUF;      // 2 x (16 x 36)
    float* lsm = sm;                // aliased after mainloop

    __shared__ float s_sums[EXPN];
    __shared__ float s_cnt[EXPN];

    const int lane = threadIdx.x;
    const int tile = blockIdx.x;
    const int tok0 = tile * TOKT;

    if (lane < 32) { s_sums[lane] = 0.f; s_sums[lane + 32] = 0.f;
                     s_cnt[lane] = 0.f;  s_cnt[lane + 32] = 0.f; }

    const int tok_g = lane >> 3;   // 0..3 : tokens tok_g + 4i
    const int eg    = lane & 7;    // experts eg + 8j

    unsigned long long acc[4][8];
#pragma unroll
    for (int i = 0; i < 4; i++)
#pragma unroll
        for (int j = 0; j < 8; j++) acc[i][j] = 0ULL;

    auto load_chunk = [&](int c) {
        const int par = c & 1;
        float* wd = ws + par * WBUF;
        float* xd = xs + par * XBUF;
#pragma unroll
        for (int j = 0; j < 16; j++) {        // W: 512 float4
            int idx = lane + j * 32;
            int e = idx >> 3, q = idx & 7;
            cp16(wd + e * WROW + q * 4, w + (size_t)e * CDIM + c * KC + q * 4);
        }
#pragma unroll
        for (int j = 0; j < 4; j++) {         // x: 128 float4
            int idx = lane + j * 32;
            int t = idx >> 3, q = idx & 7;
            cp16(xd + t * WROW + q * 4, x + (size_t)(tok0 + t) * CDIM + c * KC + q * 4);
        }
        CP_COMMIT();
    };

    load_chunk(0);
    load_chunk(1);

    for (int c = 0; c < NCHK; c++) {
        if (c + 1 < NCHK) asm volatile("cp.async.wait_group 1;\n" ::: "memory");
        else              asm volatile("cp.async.wait_group 0;\n" ::: "memory");

        const int par = c & 1;
        const float* wd = ws + par * WBUF;
        const float* xd = xs + par * XBUF;

#pragma unroll
        for (int q = 0; q < 8; q++) {   // k4 steps within chunk
            ulonglong2 xv[4], wv[8];
#pragma unroll
            for (int i = 0; i < 4; i++)
                xv[i] = *(const ulonglong2*)(xd + (tok_g + 4 * i) * WROW + q * 4);
#pragma unroll
            for (int j = 0; j < 8; j++)
                wv[j] = *(const ulonglong2*)(wd + (eg + 8 * j) * WROW + q * 4);
            // per-acc order identical to R1: pair(k0,k1) then pair(k2,k3), k ascending
#pragma unroll
            for (int i = 0; i < 4; i++)
#pragma unroll
                for (int j = 0; j < 8; j++) ffma2(acc[i][j], xv[i].x, wv[j].x);
#pragma unroll
            for (int i = 0; i < 4; i++)
#pragma unroll
                for (int j = 0; j < 8; j++) ffma2(acc[i][j], xv[i].y, wv[j].y);
        }
        if (c + 2 < NCHK) load_chunk(c + 2);
    }
    __syncwarp();

    // logits -> smem (lo+hi = R1's even-chain + odd-chain sum)
#pragma unroll
    for (int i = 0; i < 4; i++)
#pragma unroll
        for (int j = 0; j < 8; j++) {
            float lo, hi;
            unpk(acc[i][j], lo, hi);
            lsm[(tok_g + 4 * i) * LSTRE + eg + 8 * j] = lo + hi;
        }
    __syncwarp();

    // ---- per-token epilogue (R1-verbatim) ----
    if (lane < TOKT) {
        float* row = lsm + lane * LSTRE;

        float v0 = -1e38f, v1 = -1e38f, v2 = -1e38f, v3 = -1e38f, v4 = -1e38f, v5 = -1e38f;
        int   i0 = 0, i1 = 0, i2 = 0, i3 = 0, i4 = 0, i5 = 0;
        for (int e = 0; e < EXPN; e++) {
            float l = row[e];
            if (l > v5) {
                v5 = l; i5 = e;
                if (v5 > v4) { float t = v4; v4 = v5; v5 = t; int u = i4; i4 = i5; i5 = u; }
                if (v4 > v3) { float t = v3; v3 = v4; v4 = t; int u = i3; i3 = i4; i4 = u; }
                if (v3 > v2) { float t = v2; v2 = v3; v3 = t; int u = i2; i2 = i3; i3 = u; }
                if (v2 > v1) { float t = v1; v1 = v2; v2 = t; int u = i1; i1 = i2; i2 = u; }
                if (v1 > v0) { float t = v0; v0 = v1; v1 = t; int u = i0; i0 = i1; i1 = u; }
            }
        }

        float m = v0;
        float ssum = 0.f;
        for (int e = 0; e < EXPN; e++) {
            float p = expf(row[e] - m);
            ssum += p;
            row[e] = p;
        }
        float inv = 1.0f / ssum;

        const size_t g = (size_t)(tok0 + lane);
        float* out_idx = out;
        float* out_wgt = out + (size_t)BT * TOPK;

        out_idx[g * TOPK + 0] = (float)i0;
        out_idx[g * TOPK + 1] = (float)i1;
        out_idx[g * TOPK + 2] = (float)i2;
        out_idx[g * TOPK + 3] = (float)i3;
        out_idx[g * TOPK + 4] = (float)i4;
        out_idx[g * TOPK + 5] = (float)i5;

        out_wgt[g * TOPK + 0] = row[i0] * inv;
        out_wgt[g * TOPK + 1] = row[i1] * inv;
        out_wgt[g * TOPK + 2] = row[i2] * inv;
        out_wgt[g * TOPK + 3] = row[i3] * inv;
        out_wgt[g * TOPK + 4] = row[i4] * inv;
        out_wgt[g * TOPK + 5] = row[i5] * inv;

        for (int jj = 0; jj < EXPN; jj++) {
            int e = (lane + jj) & (EXPN - 1);
            atomicAdd(&s_sums[e], row[e] * inv);
        }
        atomicAdd(&s_cnt[i0], 1.0f);
        atomicAdd(&s_cnt[i1], 1.0f);
        atomicAdd(&s_cnt[i2], 1.0f);
        atomicAdd(&s_cnt[i3], 1.0f);
        atomicAdd(&s_cnt[i4], 1.0f);
        atomicAdd(&s_cnt[i5], 1.0f);
    }
    __syncwarp();

    // per-tile partials (overwrite; no zero kernel needed)
    g_part[tile * EXPN + lane]      = s_sums[lane];
    g_part[tile * EXPN + lane + 32] = s_sums[lane + 32];
    g_pcnt[tile * EXPN + lane]      = s_cnt[lane];
    g_pcnt[tile * EXPN + lane + 32] = s_cnt[lane + 32];
}

// ---------------- aux: MLP-unrolled reduce of per-tile partials ----------------
__global__ void aux_kernel(float* __restrict__ out) {
    __shared__ float red[256];
    const int tid = threadIdx.x;
    const int b = tid >> 6;
    const int e = tid & 63;

    const float* gp = g_part + (size_t)(b * 256) * EXPN + e;
    const float* gc = g_pcnt + (size_t)(b * 256) * EXPN + e;
    float s0 = 0.f, s1 = 0.f, s2 = 0.f, s3 = 0.f;
    float c0 = 0.f, c1 = 0.f, c2 = 0.f, c3 = 0.f;
#pragma unroll 8
    for (int t = 0; t < 256; t += 4) {
        s0 += gp[(t + 0) * EXPN];
        s1 += gp[(t + 1) * EXPN];
        s2 += gp[(t + 2) * EXPN];
        s3 += gp[(t + 3) * EXPN];
        c0 += gc[(t + 0) * EXPN];
        c1 += gc[(t + 1) * EXPN];
        c2 += gc[(t + 2) * EXPN];
        c3 += gc[(t + 3) * EXPN];
    }
    red[tid] = ((s0 + s1) + (s2 + s3)) * ((c0 + c1) + (c2 + c3));
    __syncthreads();
#pragma unroll
    for (int s = 128; s > 0; s >>= 1) {
        if (tid < s) red[tid] += red[tid + s];
        __syncthreads();
    }
    if (tid == 0) {
        const float scale = (float)(0.001 * 64.0 / ((double)4 * 4096.0 * 6.0 * 4096.0));
        out[(size_t)BT * 12] = red[0] * scale;
    }
}

extern "C" void kernel_launch(void* const* d_in, const int* in_sizes, int n_in,
                              void* d_out, int out_size) {
    const float* x = (const float*)d_in[0];
    const float* w = (const float*)d_in[1];
    float* out = (float*)d_out;

    cudaFuncSetAttribute(gate_kernel, cudaFuncAttributeMaxDynamicSharedMemorySize, SMEM_BYTES);
    cudaFuncSetAttribute(gate_kernel, cudaFuncAttributePreferredSharedMemoryCarveout, 100);

    gate_kernel<<<NTILE, TPB, SMEM_BYTES>>>(x, w, out);
    aux_kernel<<<1, 256>>>(out);
}